// round 1
// baseline (speedup 1.0000x reference)
#include <cuda_runtime.h>

// Problem constants
#define NUM_U   4
#define NUM_NT  8
#define NPER    (128LL * 49152LL)      // elements per user = 6,291,456
#define N4      (NPER / 4)             // float4 elements per user = 1,572,864

// Precomputed coefficients: out[u] = sum_v A[u][v] * x[v] + S[u] * noise[u]
__device__ float g_A[NUM_U * NUM_U];
__device__ float g_S[NUM_U];

__global__ void precompute_coeffs(const float* __restrict__ W,   // [NT, U]
                                  const float* __restrict__ H,   // [NT, U]
                                  const float* __restrict__ P,   // [U]
                                  const float* __restrict__ stddev) // [U]
{
    if (threadIdx.x != 0 || blockIdx.x != 0) return;

    float sqrtP[NUM_U];
    #pragma unroll
    for (int u = 0; u < NUM_U; u++) sqrtP[u] = sqrtf(P[u]);

    // G[u][v] = sum_n H[n,u] * W[n,v]
    float G[NUM_U][NUM_U];
    #pragma unroll
    for (int u = 0; u < NUM_U; u++) {
        #pragma unroll
        for (int v = 0; v < NUM_U; v++) {
            float acc = 0.f;
            #pragma unroll
            for (int n = 0; n < NUM_NT; n++)
                acc += H[n * NUM_U + u] * W[n * NUM_U + v];
            G[u][v] = acc;
        }
    }

    #pragma unroll
    for (int u = 0; u < NUM_U; u++) {
        float amp = sqrtP[u] * G[u][u];
        float inv_amp = 1.0f / amp;
        #pragma unroll
        for (int v = 0; v < NUM_U; v++)
            g_A[u * NUM_U + v] = sqrtP[v] * G[u][v] * inv_amp;
        g_S[u] = stddev[u] * inv_amp;
    }
}

__global__ __launch_bounds__(256, 8)
void fused_miso_kernel(const float4* __restrict__ x,      // [U][N4]
                       const float4* __restrict__ noise,  // [U][N4]
                       float4* __restrict__ out)          // [U][N4]
{
    long long i = (long long)blockIdx.x * blockDim.x + threadIdx.x;
    if (i >= N4) return;

    // Load coefficients (L1-cached broadcast loads, held in registers)
    float a[NUM_U * NUM_U];
    #pragma unroll
    for (int k = 0; k < NUM_U * NUM_U; k++) a[k] = g_A[k];
    float s[NUM_U];
    #pragma unroll
    for (int u = 0; u < NUM_U; u++) s[u] = g_S[u];

    // Read x for all 4 users at this position
    float4 xv[NUM_U];
    #pragma unroll
    for (int v = 0; v < NUM_U; v++)
        xv[v] = x[(long long)v * N4 + i];

    // Produce all 4 user outputs
    #pragma unroll
    for (int u = 0; u < NUM_U; u++) {
        float4 nv = noise[(long long)u * N4 + i];
        float4 o;
        o.x = fmaf(s[u], nv.x, a[u*NUM_U+0]*xv[0].x + a[u*NUM_U+1]*xv[1].x + a[u*NUM_U+2]*xv[2].x + a[u*NUM_U+3]*xv[3].x);
        o.y = fmaf(s[u], nv.y, a[u*NUM_U+0]*xv[0].y + a[u*NUM_U+1]*xv[1].y + a[u*NUM_U+2]*xv[2].y + a[u*NUM_U+3]*xv[3].y);
        o.z = fmaf(s[u], nv.z, a[u*NUM_U+0]*xv[0].z + a[u*NUM_U+1]*xv[1].z + a[u*NUM_U+2]*xv[2].z + a[u*NUM_U+3]*xv[3].z);
        o.w = fmaf(s[u], nv.w, a[u*NUM_U+0]*xv[0].w + a[u*NUM_U+1]*xv[1].w + a[u*NUM_U+2]*xv[2].w + a[u*NUM_U+3]*xv[3].w);
        out[(long long)u * N4 + i] = o;
    }
}

extern "C" void kernel_launch(void* const* d_in, const int* in_sizes, int n_in,
                              void* d_out, int out_size)
{
    // Input order per reference setup_inputs(): x, W, H, P, stddev, noise
    const float* x      = (const float*)d_in[0];
    const float* W      = (const float*)d_in[1];
    const float* H      = (const float*)d_in[2];
    const float* P      = (const float*)d_in[3];
    const float* stddev = (const float*)d_in[4];
    const float* noise  = (const float*)d_in[5];
    float* out = (float*)d_out;

    precompute_coeffs<<<1, 32>>>(W, H, P, stddev);

    const int threads = 256;
    const long long blocks = (N4 + threads - 1) / threads;  // 6144
    fused_miso_kernel<<<(unsigned)blocks, threads>>>(
        (const float4*)x, (const float4*)noise, (float4*)out);
}

// round 2
// speedup vs baseline: 1.0788x; 1.0788x over previous
#include <cuda_runtime.h>

// Problem constants
#define NUM_U    4
#define NUM_NT   8
#define NPER     (128 * 49152)        // elements per user = 6,291,456
#define N4       (NPER / 4)           // float4 elements per user = 1,572,864
#define THREADS  256
#define IPT      4                    // float4 positions per thread
#define GRID     (N4 / (THREADS * IPT))   // 1536 blocks, exact cover

// Single fused kernel:
//   out[u,i] = sum_v A[u][v] * x[v,i] + S[u] * noise[u,i]
// Coefficients computed per-block in shared memory (removes the extra launch).
__global__ __launch_bounds__(THREADS)
void fused_miso_kernel(const float4* __restrict__ x,      // [U][N4]
                       const float4* __restrict__ noise,  // [U][N4]
                       float4* __restrict__ out,          // [U][N4]
                       const float* __restrict__ W,       // [NT, U]
                       const float* __restrict__ H,       // [NT, U]
                       const float* __restrict__ P,       // [U]
                       const float* __restrict__ stddev)  // [U]
{
    __shared__ float sG[NUM_U * NUM_U];
    __shared__ float sA[NUM_U * NUM_U];
    __shared__ float sS[NUM_U];

    const int t = threadIdx.x;

    // ---- per-block coefficient computation (16 threads, ~200 cycles) ----
    if (t < NUM_U * NUM_U) {
        const int u = t >> 2, v = t & 3;
        float acc = 0.f;
        #pragma unroll
        for (int n = 0; n < NUM_NT; n++)
            acc += H[n * NUM_U + u] * W[n * NUM_U + v];
        sG[t] = acc;
    }
    __syncthreads();
    if (t < NUM_U * NUM_U) {
        const int u = t >> 2, v = t & 3;
        const float inv_amp = 1.0f / (sqrtf(P[u]) * sG[u * NUM_U + u]);
        sA[t] = sqrtf(P[v]) * sG[t] * inv_amp;
        if (v == 0) sS[u] = stddev[u] * inv_amp;
    }
    __syncthreads();

    float a[NUM_U * NUM_U];
    #pragma unroll
    for (int k = 0; k < NUM_U * NUM_U; k++) a[k] = sA[k];
    float s[NUM_U];
    #pragma unroll
    for (int u = 0; u < NUM_U; u++) s[u] = sS[u];

    // ---- streaming main loop: 4 positions per thread, 32-bit indexing ----
    const unsigned total = GRID * THREADS;                  // 393,216
    const unsigned i0 = blockIdx.x * THREADS + t;

    #pragma unroll
    for (int k = 0; k < IPT; k++) {
        const unsigned i = i0 + (unsigned)k * total;        // < N4 always

        float4 xv[NUM_U];
        #pragma unroll
        for (int v = 0; v < NUM_U; v++)
            xv[v] = x[v * (unsigned)N4 + i];

        #pragma unroll
        for (int u = 0; u < NUM_U; u++) {
            const float4 nv = noise[u * (unsigned)N4 + i];
            const float a0 = a[u*NUM_U+0], a1 = a[u*NUM_U+1],
                        a2 = a[u*NUM_U+2], a3 = a[u*NUM_U+3];
            float4 o;
            o.x = fmaf(s[u], nv.x, fmaf(a0, xv[0].x, fmaf(a1, xv[1].x, fmaf(a2, xv[2].x, a3 * xv[3].x))));
            o.y = fmaf(s[u], nv.y, fmaf(a0, xv[0].y, fmaf(a1, xv[1].y, fmaf(a2, xv[2].y, a3 * xv[3].y))));
            o.z = fmaf(s[u], nv.z, fmaf(a0, xv[0].z, fmaf(a1, xv[1].z, fmaf(a2, xv[2].z, a3 * xv[3].z))));
            o.w = fmaf(s[u], nv.w, fmaf(a0, xv[0].w, fmaf(a1, xv[1].w, fmaf(a2, xv[2].w, a3 * xv[3].w))));
            out[u * (unsigned)N4 + i] = o;
        }
    }
}

extern "C" void kernel_launch(void* const* d_in, const int* in_sizes, int n_in,
                              void* d_out, int out_size)
{
    // Input order per reference setup_inputs(): x, W, H, P, stddev, noise
    const float* x      = (const float*)d_in[0];
    const float* W      = (const float*)d_in[1];
    const float* H      = (const float*)d_in[2];
    const float* P      = (const float*)d_in[3];
    const float* stddev = (const float*)d_in[4];
    const float* noise  = (const float*)d_in[5];
    float* out = (float*)d_out;

    fused_miso_kernel<<<GRID, THREADS>>>(
        (const float4*)x, (const float4*)noise, (float4*)out,
        W, H, P, stddev);
}

// round 3
// speedup vs baseline: 1.1231x; 1.0410x over previous
#include <cuda_runtime.h>

// Problem constants
#define NUM_U    4
#define NUM_NT   8
#define NPER     (128 * 49152)        // elements per user = 6,291,456
#define N4       (NPER / 4)           // float4 elements per user = 1,572,864
#define THREADS  256
#define IPT      4                    // float4 positions per thread
#define GRID     (N4 / (THREADS * IPT))   // 1536 blocks, exact cover

// out[u,i] = sum_v A[u][v] * x[v,i] + S[u] * noise[u,i]
__global__ __launch_bounds__(THREADS)
void fused_miso_kernel(const float4* __restrict__ x,      // [U][N4]
                       const float4* __restrict__ noise,  // [U][N4]
                       float4* __restrict__ out,          // [U][N4]
                       const float* __restrict__ W,       // [NT, U]
                       const float* __restrict__ H,       // [NT, U]
                       const float* __restrict__ P,       // [U]
                       const float* __restrict__ stddev)  // [U]
{
    __shared__ float sG[NUM_U * NUM_U];
    __shared__ float sA[NUM_U * NUM_U];
    __shared__ float sS[NUM_U];

    const int t = threadIdx.x;

    // ---- per-block coefficient computation (16 threads, ~200 cycles) ----
    if (t < NUM_U * NUM_U) {
        const int u = t >> 2, v = t & 3;
        float acc = 0.f;
        #pragma unroll
        for (int n = 0; n < NUM_NT; n++)
            acc += H[n * NUM_U + u] * W[n * NUM_U + v];
        sG[t] = acc;
    }
    __syncthreads();
    if (t < NUM_U * NUM_U) {
        const int u = t >> 2, v = t & 3;
        const float inv_amp = 1.0f / (sqrtf(P[u]) * sG[u * NUM_U + u]);
        sA[t] = sqrtf(P[v]) * sG[t] * inv_amp;
        if (v == 0) sS[u] = stddev[u] * inv_amp;
    }
    __syncthreads();

    float a[NUM_U * NUM_U];
    #pragma unroll
    for (int k = 0; k < NUM_U * NUM_U; k++) a[k] = sA[k];
    float s[NUM_U];
    #pragma unroll
    for (int u = 0; u < NUM_U; u++) s[u] = sS[u];

    // ---- streaming main loop ----
    const unsigned total = GRID * THREADS;                  // 393,216
    const unsigned i0 = blockIdx.x * THREADS + t;

    #pragma unroll
    for (int k = 0; k < IPT; k++) {
        const unsigned i = i0 + (unsigned)k * total;        // < N4 always

        // Front-batch ALL 8 loads (streaming, evict-first) before any math.
        float4 xv[NUM_U];
        float4 nv[NUM_U];
        #pragma unroll
        for (int v = 0; v < NUM_U; v++)
            xv[v] = __ldcs(&x[v * (unsigned)N4 + i]);
        #pragma unroll
        for (int u = 0; u < NUM_U; u++)
            nv[u] = __ldcs(&noise[u * (unsigned)N4 + i]);

        #pragma unroll
        for (int u = 0; u < NUM_U; u++) {
            const float a0 = a[u*NUM_U+0], a1 = a[u*NUM_U+1],
                        a2 = a[u*NUM_U+2], a3 = a[u*NUM_U+3];
            float4 o;
            o.x = fmaf(s[u], nv[u].x, fmaf(a0, xv[0].x, fmaf(a1, xv[1].x, fmaf(a2, xv[2].x, a3 * xv[3].x))));
            o.y = fmaf(s[u], nv[u].y, fmaf(a0, xv[0].y, fmaf(a1, xv[1].y, fmaf(a2, xv[2].y, a3 * xv[3].y))));
            o.z = fmaf(s[u], nv[u].z, fmaf(a0, xv[0].z, fmaf(a1, xv[1].z, fmaf(a2, xv[2].z, a3 * xv[3].z))));
            o.w = fmaf(s[u], nv[u].w, fmaf(a0, xv[0].w, fmaf(a1, xv[1].w, fmaf(a2, xv[2].w, a3 * xv[3].w))));
            __stcs(&out[u * (unsigned)N4 + i], o);
        }
    }
}

extern "C" void kernel_launch(void* const* d_in, const int* in_sizes, int n_in,
                              void* d_out, int out_size)
{
    // Input order per reference setup_inputs(): x, W, H, P, stddev, noise
    const float* x      = (const float*)d_in[0];
    const float* W      = (const float*)d_in[1];
    const float* H      = (const float*)d_in[2];
    const float* P      = (const float*)d_in[3];
    const float* stddev = (const float*)d_in[4];
    const float* noise  = (const float*)d_in[5];
    float* out = (float*)d_out;

    fused_miso_kernel<<<GRID, THREADS>>>(
        (const float4*)x, (const float4*)noise, (float4*)out,
        W, H, P, stddev);
}